// round 8
// baseline (speedup 1.0000x reference)
#include <cuda_runtime.h>
#include <cstdint>
#include <math.h>

// ---------------- problem constants (fixed by reference) ----------------
#define NG   100
#define NPG  500
#define EPG  4000
#define NN   (NG*NPG)      // 50000 nodes
#define NE   (NG*EPG)      // 400000 edges
#define HID  128
#define H4   512
#define PQW  1024          // P (512) || Q (512)
#define KSEL 2000          // ceil(0.5 * 4000)

// output layout (float32, concatenated in reference return order)
#define O_ATT 0
#define O_CW  (NE)
#define O_SW  (2*NE)
#define O_CM  (3*NE)
#define O_EI  (4*NE)           // [2,E]: new_row then new_col
#define O_NM  (6*NE)
#define O_CX  (6*NE + NN)

// ---------------- scratch (__device__ globals; no allocation) ----------------
__device__ float         g_PQ[(size_t)NN * PQW];    // ~205 MB
__device__ float         g_ehi[(size_t)NN * HID];   // 25.6 MB
__device__ float         g_elo[(size_t)NN * HID];   // 25.6 MB
__device__ float         g_wthi[2 * H4 * HID];      // transposed W halves [half][n][k], tf32-hi
__device__ float         g_wtlo[2 * H4 * HID];      // tf32-lo
__device__ unsigned char g_cmask[NE];
__device__ int           g_nm[NN];
__device__ int           g_scan[NN];
__device__ int           g_newid[NN];
__device__ int           g_bsum[128];

// ---------------- tf32 split helper ----------------
__device__ __forceinline__ float to_tf32(float x) {
    float r;
    asm("cvt.rna.tf32.f32 %0, %1;" : "=f"(r) : "f"(x));
    return r;
}

// ---------------- ordered-key helpers ----------------
__device__ __forceinline__ unsigned int f2k(float f) {
    unsigned int u = __float_as_uint(f);
    return (u & 0x80000000u) ? ~u : (u | 0x80000000u);
}
__device__ __forceinline__ float k2f(unsigned int k) {
    unsigned int u = (k & 0x80000000u) ? (k & 0x7FFFFFFFu) : ~k;
    return __uint_as_float(u);
}

// ---------------- warp-level tf32 MMA (baseline PTX) ----------------
__device__ __forceinline__ void mma_tf32(float& d0, float& d1, float& d2, float& d3,
                                         uint32_t a0, uint32_t a1, uint32_t a2, uint32_t a3,
                                         uint32_t b0, uint32_t b1) {
    asm volatile(
        "mma.sync.aligned.m16n8k8.row.col.f32.tf32.tf32.f32 "
        "{%0,%1,%2,%3}, {%4,%5,%6,%7}, {%8,%9}, {%0,%1,%2,%3};"
        : "+f"(d0), "+f"(d1), "+f"(d2), "+f"(d3)
        : "r"(a0), "r"(a1), "r"(a2), "r"(a3), "r"(b0), "r"(b1));
}

// ---------------- K0: zero node-mask ----------------
__global__ void k_zero_nm() {
    int n = blockIdx.x * blockDim.x + threadIdx.x;
    if (n < NN) g_nm[n] = 0;
}

// ---------------- K-split: emb -> tf32 hi/lo ----------------
__global__ void k_split_emb(const float* __restrict__ emb) {
    int i = blockIdx.x * blockDim.x + threadIdx.x;      // float4 index over NN*HID/4
    if (i >= NN * HID / 4) return;
    float4 v = ((const float4*)emb)[i];
    float4 h, l;
    h.x = to_tf32(v.x); l.x = to_tf32(v.x - h.x);
    h.y = to_tf32(v.y); l.y = to_tf32(v.y - h.y);
    h.z = to_tf32(v.z); l.z = to_tf32(v.z - h.z);
    h.w = to_tf32(v.w); l.w = to_tf32(v.w - h.w);
    ((float4*)g_ehi)[i] = h;
    ((float4*)g_elo)[i] = l;
}

// ---------------- K-split: W1 -> transposed tf32 hi/lo  wt[half][n][k] ----------------
__global__ void k_split_w(const float* __restrict__ W1) {
    int idx = blockIdx.x * blockDim.x + threadIdx.x;    // over 256*512
    if (idx >= 2 * HID * H4) return;
    int k = idx >> 9;          // 0..255
    int n = idx & 511;
    float v = W1[idx];
    float h = to_tf32(v);
    float l = to_tf32(v - h);
    int half = k >> 7;
    int kk = k & 127;
    int d = (half * H4 + n) * HID + kk;
    g_wthi[d] = h;
    g_wtlo[d] = l;
}

// ---------------- K1: 3xTF32 GEMM via mma.sync, pass-split MMA order ----------------
// grid (8, 391): x = 128-wide n-tile of PQ, y = 128-row m-tile.
// CTA 128x128, 8 warps, warp = 64x32 (4x4 m16n8 tiles).
// B (128n x 128k, hi+lo) resident (stride 132); A (128m x 32k hi+lo) staged per chunk (stride 36).
// Per k8-step: 3 passes (ah*bh, ah*bl, al*bh), 16 independent MMAs per pass -> no RAW chains.
#define KCH   32
#define ASTR  36
#define BSTR  132
#define SB_HI 0
#define SB_LO (128*BSTR)               // 16896 floats
#define SA_HI (2*128*BSTR)             // 33792
#define SA_LO (SA_HI + 128*ASTR)
#define GEMM_DYN ((2*128*BSTR + 2*128*ASTR)*4)   // 172032 bytes

extern __shared__ float gsm[];

__global__ __launch_bounds__(256, 1) void k_gemm_mma(const float* __restrict__ b1) {
    int tid   = threadIdx.x;
    int wid   = tid >> 5;
    int lane  = tid & 31;
    int gquad = lane >> 2;      // groupID 0..7
    int tg    = lane & 3;       // thread-in-group 0..3
    int nbase = blockIdx.x * 128;
    int mbase = blockIdx.y * 128;

    int warpM = wid & 1;        // 2 x 64 rows
    int warpN = wid >> 1;       // 4 x 32 cols

    int half   = nbase >> 9;                 // 0 = P, 1 = Q
    int nlocal = nbase & 511;
    const float* wth = g_wthi + ((size_t)half * H4 + nlocal) * HID;
    const float* wtl = g_wtlo + ((size_t)half * H4 + nlocal) * HID;

    // ---- stage B (hi+lo, full K) once ----
    #pragma unroll
    for (int l = 0; l < 16; l++) {
        int t   = tid + l * 256;          // 0..4095 float4s
        int row = t >> 5;                 // n 0..127
        int q   = t & 31;
        *(float4*)(gsm + SB_HI + row * BSTR + q * 4) =
            *(const float4*)(wth + (size_t)row * HID + q * 4);
        *(float4*)(gsm + SB_LO + row * BSTR + q * 4) =
            *(const float4*)(wtl + (size_t)row * HID + q * 4);
    }

    float acc[4][4][4];
    #pragma unroll
    for (int i = 0; i < 4; i++)
        #pragma unroll
        for (int j = 0; j < 4; j++)
            #pragma unroll
            for (int r = 0; r < 4; r++) acc[i][j][r] = 0.f;

    for (int kc = 0; kc < 4; kc++) {
        // ---- stage A chunk (hi+lo) ----
        if (kc > 0) __syncthreads();
        #pragma unroll
        for (int l = 0; l < 4; l++) {
            int t   = tid + l * 256;
            int row = t >> 3;
            int q   = t & 7;
            int gm  = mbase + row;
            float4 vh = make_float4(0.f, 0.f, 0.f, 0.f), vl = vh;
            if (gm < NN) {
                vh = *(const float4*)(g_ehi + (size_t)gm * HID + kc * KCH + q * 4);
                vl = *(const float4*)(g_elo + (size_t)gm * HID + kc * KCH + q * 4);
            }
            *(float4*)(gsm + SA_HI + row * ASTR + q * 4) = vh;
            *(float4*)(gsm + SA_LO + row * ASTR + q * 4) = vl;
        }
        __syncthreads();

        // ---- compute: 4 k8-steps, 3 dependency-free passes each ----
        #pragma unroll
        for (int ks = 0; ks < 4; ks++) {
            int k0 = ks * 8 + tg;                 // local k in A chunk
            int kg = kc * KCH + k0;               // global k for B
            uint32_t ah[4][4], al[4][4];
            #pragma unroll
            for (int i = 0; i < 4; i++) {
                int r0 = warpM * 64 + i * 16 + gquad;
                const float* pa = gsm + r0 * ASTR + k0;
                ah[i][0] = __float_as_uint(pa[SA_HI]);
                ah[i][1] = __float_as_uint(pa[SA_HI + 8 * ASTR]);
                ah[i][2] = __float_as_uint(pa[SA_HI + 4]);
                ah[i][3] = __float_as_uint(pa[SA_HI + 8 * ASTR + 4]);
                al[i][0] = __float_as_uint(pa[SA_LO]);
                al[i][1] = __float_as_uint(pa[SA_LO + 8 * ASTR]);
                al[i][2] = __float_as_uint(pa[SA_LO + 4]);
                al[i][3] = __float_as_uint(pa[SA_LO + 8 * ASTR + 4]);
            }
            uint32_t bh[4][2], bl[4][2];
            #pragma unroll
            for (int j = 0; j < 4; j++) {
                int n0 = warpN * 32 + j * 8 + gquad;
                const float* pb = gsm + n0 * BSTR + kg;
                bh[j][0] = __float_as_uint(pb[SB_HI]);
                bh[j][1] = __float_as_uint(pb[SB_HI + 4]);
                bl[j][0] = __float_as_uint(pb[SB_LO]);
                bl[j][1] = __float_as_uint(pb[SB_LO + 4]);
            }
            // pass 1: ah * bh  (16 independent MMAs)
            #pragma unroll
            for (int j = 0; j < 4; j++)
                #pragma unroll
                for (int i = 0; i < 4; i++) {
                    float* d = acc[i][j];
                    mma_tf32(d[0], d[1], d[2], d[3],
                             ah[i][0], ah[i][1], ah[i][2], ah[i][3], bh[j][0], bh[j][1]);
                }
            // pass 2: ah * bl
            #pragma unroll
            for (int j = 0; j < 4; j++)
                #pragma unroll
                for (int i = 0; i < 4; i++) {
                    float* d = acc[i][j];
                    mma_tf32(d[0], d[1], d[2], d[3],
                             ah[i][0], ah[i][1], ah[i][2], ah[i][3], bl[j][0], bl[j][1]);
                }
            // pass 3: al * bh
            #pragma unroll
            for (int j = 0; j < 4; j++)
                #pragma unroll
                for (int i = 0; i < 4; i++) {
                    float* d = acc[i][j];
                    mma_tf32(d[0], d[1], d[2], d[3],
                             al[i][0], al[i][1], al[i][2], al[i][3], bh[j][0], bh[j][1]);
                }
        }
    }

    // ---- epilogue: add b1 (P half), store float2 pairs ----
    #pragma unroll
    for (int j = 0; j < 4; j++) {
        int col = nbase + warpN * 32 + j * 8 + 2 * tg;   // even
        float2 bv = make_float2(0.f, 0.f);
        if (col < H4) bv = *(const float2*)(b1 + col);
        #pragma unroll
        for (int i = 0; i < 4; i++) {
            int row0 = mbase + warpM * 64 + i * 16 + gquad;
            float* d = acc[i][j];
            if (row0 < NN)
                *(float2*)(g_PQ + (size_t)row0 * PQW + col) =
                    make_float2(d[0] + bv.x, d[1] + bv.y);
            if (row0 + 8 < NN)
                *(float2*)(g_PQ + (size_t)(row0 + 8) * PQW + col) =
                    make_float2(d[2] + bv.x, d[3] + bv.y);
        }
    }
}

// ---------------- K2: edge attention, one warp per edge (b1 pre-folded into P) ----------------
__global__ __launch_bounds__(256) void k_edge_att(const int* __restrict__ ei,
                                                  const float* __restrict__ W2,
                                                  const float* __restrict__ b2,
                                                  float* __restrict__ out) {
    __shared__ __align__(16) float sw2[H4];
    int tid = threadIdx.x;
    for (int i = tid; i < H4; i += blockDim.x) sw2[i] = W2[i];
    __syncthreads();

    int gw   = (blockIdx.x * blockDim.x + tid) >> 5;
    int lane = tid & 31;
    if (gw >= NE) return;
    int r = ei[gw];
    int c = ei[NE + gw];
    const float4* Pr = (const float4*)(g_PQ + (size_t)r * PQW);
    const float4* Qr = (const float4*)(g_PQ + (size_t)c * PQW + H4);
    const float4* W4 = (const float4*)sw2;

    float acc = 0.f;
    #pragma unroll
    for (int it = 0; it < 4; it++) {
        int j4 = it * 32 + lane;
        float4 p = Pr[j4];
        float4 q = Qr[j4];
        float4 ww = W4[j4];
        acc += ww.x * fmaxf(p.x + q.x, 0.f);
        acc += ww.y * fmaxf(p.y + q.y, 0.f);
        acc += ww.z * fmaxf(p.z + q.z, 0.f);
        acc += ww.w * fmaxf(p.w + q.w, 0.f);
    }
    #pragma unroll
    for (int off = 16; off > 0; off >>= 1)
        acc += __shfl_xor_sync(0xFFFFFFFFu, acc, off);
    if (lane == 0) out[O_ATT + gw] = acc + b2[0];
}

// ---------------- K3: per-graph top-k radix select (512 thr, shuffle scans) ----------------
__global__ __launch_bounds__(512) void k_select(const int* __restrict__ ei,
                                                float* __restrict__ out) {
    __shared__ unsigned int skey[EPG];     // 16KB
    __shared__ int hist[256];
    __shared__ int wtmp[16];
    __shared__ unsigned int s_prefix;
    __shared__ int s_kleft;

    int g    = blockIdx.x;
    int tid  = threadIdx.x;
    int lane = tid & 31;
    int wid  = tid >> 5;
    int base = g * EPG;

    for (int i = tid; i < EPG; i += 512) skey[i] = f2k(out[O_ATT + base + i]);
    __syncthreads();

    unsigned int prefix = 0u;
    int kleft = KSEL;
    #pragma unroll
    for (int pass = 3; pass >= 0; pass--) {
        int shift = pass * 8;
        if (tid < 256) hist[tid] = 0;
        __syncthreads();
        unsigned int maskHigh = (pass == 3) ? 0u : (0xFFFFFFFFu << (shift + 8));
        for (int i = tid; i < EPG; i += 512) {
            unsigned int k = skey[i];
            if ((k & maskHigh) == prefix)
                atomicAdd(&hist[(k >> shift) & 255], 1);
        }
        __syncthreads();
        int myh = 0, sfx = 0;
        if (tid < 256) {
            myh = hist[tid];
            sfx = myh;
            #pragma unroll
            for (int off = 1; off < 32; off <<= 1) {
                int t = __shfl_down_sync(0xFFFFFFFFu, sfx, off);
                if (lane + off < 32) sfx += t;
            }
            if (lane == 0) wtmp[wid] = sfx;
        }
        __syncthreads();
        if (tid < 32) {
            int v = (tid < 8) ? wtmp[tid] : 0;
            #pragma unroll
            for (int off = 1; off < 8; off <<= 1) {
                int t = __shfl_down_sync(0xFFFFFFFFu, v, off);
                if (tid + off < 8) v += t;
            }
            if (tid < 8) wtmp[8 + tid] = v;
        }
        __syncthreads();
        if (tid < 256) {
            int incl  = sfx + ((wid < 7) ? wtmp[8 + wid + 1] : 0);
            int above = incl - myh;
            if (above < kleft && incl >= kleft) {
                s_prefix = prefix | ((unsigned int)tid << shift);
                s_kleft  = kleft - above;
            }
        }
        __syncthreads();
        prefix = s_prefix;
        kleft  = s_kleft;
    }
    __syncthreads();
    unsigned int T = prefix;
    int need = kleft;

    // ordered prefix over equality flags; 512*8=4096 > EPG=4000 -> guard everything
    int start = tid * 8;
    int localEq = 0;
    #pragma unroll
    for (int i = 0; i < 8; i++) {
        int idx = start + i;
        if (idx < EPG) localEq += (skey[idx] == T);
    }
    int p = localEq;
    #pragma unroll
    for (int off = 1; off < 32; off <<= 1) {
        int t = __shfl_up_sync(0xFFFFFFFFu, p, off);
        if (lane >= off) p += t;
    }
    if (lane == 31) wtmp[wid] = p;
    __syncthreads();
    if (tid < 32) {
        int v = (tid < 16) ? wtmp[tid] : 0;
        #pragma unroll
        for (int off = 1; off < 16; off <<= 1) {
            int t = __shfl_up_sync(0xFFFFFFFFu, v, off);
            if (tid >= off) v += t;
        }
        if (tid < 16) wtmp[tid] = v;
    }
    __syncthreads();
    int run = (p - localEq) + ((wid > 0) ? wtmp[wid - 1] : 0);

    for (int i = start; i < start + 8 && i < EPG; i++) {
        unsigned int k = skey[i];
        bool causal;
        if (k > T)       causal = true;
        else if (k == T) { causal = (run < need); run++; }
        else             causal = false;
        float att = k2f(k);
        int e = base + i;
        out[O_CW + e] = causal ? att : 0.f;
        out[O_SW + e] = causal ? 0.f : att;
        out[O_CM + e] = causal ? 1.f : 0.f;
        g_cmask[e] = causal ? 1 : 0;
        if (causal) {
            g_nm[ei[e]]      = 1;
            g_nm[ei[NE + e]] = 1;
        }
    }
}

// ---------------- K4/K5: two-level scan of node mask ----------------
__global__ __launch_bounds__(512) void k_scan_a() {
    __shared__ int s[512];
    int tid = threadIdx.x;
    int n = blockIdx.x * 512 + tid;
    int x = (n < NN) ? g_nm[n] : 0;
    s[tid] = x;
    __syncthreads();
    for (int off = 1; off < 512; off <<= 1) {
        int v = (tid >= off) ? s[tid - off] : 0;
        __syncthreads();
        s[tid] += v;
        __syncthreads();
    }
    if (n < NN) g_scan[n] = s[tid];
    if (tid == 511) g_bsum[blockIdx.x] = s[511];
}

__global__ void k_scan_b(int nblk) {
    if (threadIdx.x == 0 && blockIdx.x == 0) {
        int running = 0;
        for (int b = 0; b < nblk; b++) {
            int t = g_bsum[b];
            g_bsum[b] = running;
            running += t;
        }
    }
}

// ---------------- K6: fused node finalize (new_id, node_mask) + causal_x copy ----------------
__global__ void k_nodes(const float* __restrict__ emb, float* __restrict__ out) {
    int i = blockIdx.x * blockDim.x + threadIdx.x;
    if (i >= NN * 32) return;
    int node = i >> 5;
    int nmv = g_nm[node];
    float4 v = make_float4(0.f, 0.f, 0.f, 0.f);
    if (nmv) v = ((const float4*)emb)[i];
    ((float4*)(out + O_CX))[i] = v;
    if ((i & 31) == 0) {
        out[O_NM + node] = nmv ? 1.f : 0.f;
        g_newid[node] = g_scan[node] + g_bsum[node >> 9] - 1;
    }
}

// ---------------- K7: relabeled edge index ----------------
__global__ void k_edge_out(const int* __restrict__ ei, float* __restrict__ out) {
    int e = blockIdx.x * blockDim.x + threadIdx.x;
    if (e >= NE) return;
    bool c = g_cmask[e] != 0;
    int r = ei[e], cc = ei[NE + e];
    out[O_EI + e]      = c ? (float)g_newid[r]  : -1.f;
    out[O_EI + NE + e] = c ? (float)g_newid[cc] : -1.f;
}

// ---------------- launch ----------------
extern "C" void kernel_launch(void* const* d_in, const int* in_sizes, int n_in,
                              void* d_out, int out_size) {
    const float* emb = (const float*)d_in[0];
    const int*   ei  = (const int*)d_in[1];
    // d_in[2] = node_batch (implied by layout: graph = e / EPG)
    const float* W1  = (const float*)d_in[3];
    const float* b1  = (const float*)d_in[4];
    const float* W2  = (const float*)d_in[5];
    const float* b2  = (const float*)d_in[6];
    float* out = (float*)d_out;

    k_zero_nm<<<(NN + 255) / 256, 256>>>();
    k_split_emb<<<(NN * HID / 4 + 255) / 256, 256>>>(emb);
    k_split_w<<<(2 * HID * H4 + 255) / 256, 256>>>(W1);

    cudaFuncSetAttribute(k_gemm_mma, cudaFuncAttributeMaxDynamicSharedMemorySize, GEMM_DYN);
    dim3 ggrid(PQW / 128, (NN + 127) / 128);   // (8, 391)
    k_gemm_mma<<<ggrid, 256, GEMM_DYN>>>(b1);

    k_edge_att<<<(NE * 32 + 255) / 256, 256>>>(ei, W2, b2, out);

    k_select<<<NG, 512>>>(ei, out);

    int nblk = (NN + 511) / 512;            // 98
    k_scan_a<<<nblk, 512>>>();
    k_scan_b<<<1, 32>>>(nblk);

    k_nodes<<<(NN * 32 + 255) / 256, 256>>>(emb, out);
    k_edge_out<<<(NE + 255) / 256, 256>>>(ei, out);
}

// round 9
// speedup vs baseline: 1.0766x; 1.0766x over previous
#include <cuda_runtime.h>
#include <cstdint>
#include <math.h>

// ---------------- problem constants (fixed by reference) ----------------
#define NG   100
#define NPG  500
#define EPG  4000
#define NN   (NG*NPG)      // 50000 nodes
#define NE   (NG*EPG)      // 400000 edges
#define HID  128
#define H4   512
#define PQW  1024          // P (512) || Q (512)
#define KSEL 2000          // ceil(0.5 * 4000)
#define MT_TOT 3125        // NN/16 m16-tiles

// output layout (float32, concatenated in reference return order)
#define O_ATT 0
#define O_CW  (NE)
#define O_SW  (2*NE)
#define O_CM  (3*NE)
#define O_EI  (4*NE)           // [2,E]: new_row then new_col
#define O_NM  (6*NE)
#define O_CX  (6*NE + NN)

// ---------------- scratch (__device__ globals; no allocation) ----------------
// A in FRAGMENT ORDER: [mt(3125)][ks(16)][lane(32)][4 floats]
__device__ float         g_ehi[(size_t)MT_TOT * 16 * 32 * 4];
__device__ float         g_elo[(size_t)MT_TOT * 16 * 32 * 4];
// B in FRAGMENT ORDER: [half(2)][nt(64)][ks(16)][lane(32)][2 floats]
__device__ float         g_wthi[2 * 64 * 16 * 32 * 2];
__device__ float         g_wtlo[2 * 64 * 16 * 32 * 2];
__device__ float         g_PQ[(size_t)NN * PQW];    // ~205 MB
__device__ unsigned char g_cmask[NE];
__device__ int           g_nm[NN];
__device__ int           g_scan[NN];
__device__ int           g_newid[NN];
__device__ int           g_bsum[128];

// ---------------- tf32 split helper ----------------
__device__ __forceinline__ float to_tf32(float x) {
    float r;
    asm("cvt.rna.tf32.f32 %0, %1;" : "=f"(r) : "f"(x));
    return r;
}

// ---------------- ordered-key helpers ----------------
__device__ __forceinline__ unsigned int f2k(float f) {
    unsigned int u = __float_as_uint(f);
    return (u & 0x80000000u) ? ~u : (u | 0x80000000u);
}
__device__ __forceinline__ float k2f(unsigned int k) {
    unsigned int u = (k & 0x80000000u) ? (k & 0x7FFFFFFFu) : ~k;
    return __uint_as_float(u);
}

// ---------------- warp-level tf32 MMA (baseline PTX) ----------------
__device__ __forceinline__ void mma_tf32(float& d0, float& d1, float& d2, float& d3,
                                         uint32_t a0, uint32_t a1, uint32_t a2, uint32_t a3,
                                         uint32_t b0, uint32_t b1) {
    asm volatile(
        "mma.sync.aligned.m16n8k8.row.col.f32.tf32.tf32.f32 "
        "{%0,%1,%2,%3}, {%4,%5,%6,%7}, {%8,%9}, {%0,%1,%2,%3};"
        : "+f"(d0), "+f"(d1), "+f"(d2), "+f"(d3)
        : "r"(a0), "r"(a1), "r"(a2), "r"(a3), "r"(b0), "r"(b1));
}

// ---------------- K0: zero node-mask ----------------
__global__ void k_zero_nm() {
    int n = blockIdx.x * blockDim.x + threadIdx.x;
    if (n < NN) g_nm[n] = 0;
}

// ---------------- K-split: emb -> tf32 hi/lo in FRAGMENT ORDER ----------------
// one warp per (mt, ks): lane (gquad,tg) packs {A[r,k], A[r+8,k], A[r,k+4], A[r+8,k+4]}
__global__ __launch_bounds__(256) void k_split_emb(const float* __restrict__ emb) {
    int wid  = threadIdx.x >> 5;
    int lane = threadIdx.x & 31;
    int gquad = lane >> 2, tg = lane & 3;
    int task = blockIdx.x * 8 + wid;            // 0 .. 3125*16-1 (exact)
    int mt = task >> 4;
    int ks = task & 15;
    int r0 = mt * 16 + gquad;
    int c0 = ks * 8 + tg;
    float v0 = emb[(size_t)r0 * HID + c0];
    float v1 = emb[(size_t)(r0 + 8) * HID + c0];
    float v2 = emb[(size_t)r0 * HID + c0 + 4];
    float v3 = emb[(size_t)(r0 + 8) * HID + c0 + 4];
    float4 h, l;
    h.x = to_tf32(v0); l.x = to_tf32(v0 - h.x);
    h.y = to_tf32(v1); l.y = to_tf32(v1 - h.y);
    h.z = to_tf32(v2); l.z = to_tf32(v2 - h.z);
    h.w = to_tf32(v3); l.w = to_tf32(v3 - h.w);
    size_t idx = ((size_t)task * 32 + lane);
    ((float4*)g_ehi)[idx] = h;
    ((float4*)g_elo)[idx] = l;
}

// ---------------- K-split: W1 -> tf32 hi/lo in FRAGMENT ORDER ----------------
// one warp per (half, nt, ks): lane packs {B[n,k], B[n,k+4]}, n=nt*8+gquad, k=half*128+ks*8+tg
__global__ __launch_bounds__(256) void k_split_w(const float* __restrict__ W1) {
    int wid  = threadIdx.x >> 5;
    int lane = threadIdx.x & 31;
    int gquad = lane >> 2, tg = lane & 3;
    int task = blockIdx.x * 8 + wid;            // 0 .. 2047 (exact)
    int half = task >> 10;
    int nt   = (task >> 4) & 63;
    int ks   = task & 15;
    int n = nt * 8 + gquad;
    int k = half * 128 + ks * 8 + tg;
    float v0 = W1[(size_t)k * H4 + n];
    float v1 = W1[(size_t)(k + 4) * H4 + n];
    float2 h, l;
    h.x = to_tf32(v0); l.x = to_tf32(v0 - h.x);
    h.y = to_tf32(v1); l.y = to_tf32(v1 - h.y);
    size_t idx = ((size_t)task * 32 + lane);
    ((float2*)g_wthi)[idx] = h;
    ((float2*)g_wtlo)[idx] = l;
}

// ---------------- K1: 3xTF32 GEMM, fragment-order operands ----------------
// grid (8, 391): x = 128-wide n-tile of PQ, y = 128-row m-tile (8 m16-tiles).
// B resident (16 nt x 16 ks, hi+lo = 128KB); A staged per 64-k chunk (8 mt x 8 ks, hi+lo = 64KB).
// Per k8-step per warp: 8 LDS.128 (A) + 8 LDS.64 (B) + 48 MMA, pass-split (no RAW chains).
#define SB_HI 0
#define SB_LO 16384
#define SA_HI 32768
#define SA_LO 40960
#define GEMM_DYN (49152*4)   // 196608 bytes

extern __shared__ float gsm[];

__global__ __launch_bounds__(256, 1) void k_gemm_mma(const float* __restrict__ b1) {
    int tid   = threadIdx.x;
    int wid   = tid >> 5;
    int lane  = tid & 31;
    int gquad = lane >> 2;
    int tg    = lane & 3;
    int nbase = blockIdx.x * 128;
    int mbase16 = blockIdx.y * 8;          // first m16-tile of this CTA

    int warpM = wid & 1;                   // 2 x 64 rows
    int warpN = wid >> 1;                  // 4 x 32 cols

    int half = nbase >> 9;                 // 0 = P, 1 = Q
    int ntb  = (nbase & 511) >> 3;         // first n8-tile within half

    // ---- stage B (16 nt x 16 ks, hi+lo) once: contiguous copy ----
    {
        size_t srcb = ((size_t)(half * 64 + ntb) * 16) * 64;   // float index
        const float4* s4h = (const float4*)(g_wthi + srcb);
        const float4* s4l = (const float4*)(g_wtlo + srcb);
        #pragma unroll
        for (int l = 0; l < 16; l++) {
            int t = tid + l * 256;                             // 0..4095 float4
            ((float4*)(gsm + SB_HI))[t] = s4h[t];
            ((float4*)(gsm + SB_LO))[t] = s4l[t];
        }
    }

    float acc[4][4][4];
    #pragma unroll
    for (int i = 0; i < 4; i++)
        #pragma unroll
        for (int j = 0; j < 4; j++)
            #pragma unroll
            for (int r = 0; r < 4; r++) acc[i][j][r] = 0.f;

    for (int kc = 0; kc < 2; kc++) {
        // ---- stage A chunk (8 mt x 8 ks, hi+lo): contiguous per-mt blocks ----
        if (kc > 0) __syncthreads();
        #pragma unroll
        for (int l = 0; l < 8; l++) {
            int t    = tid + l * 256;            // 0..2047 float4 (per hi)
            int mt   = t >> 8;                   // 0..7
            int rest = t & 255;                  // float4 within mt block
            int mtg  = mbase16 + mt;
            float4 vh = make_float4(0.f, 0.f, 0.f, 0.f), vl = vh;
            if (mtg < MT_TOT) {
                size_t src = ((size_t)(mtg * 16 + kc * 8)) * 32;   // float4 index
                vh = ((const float4*)g_ehi)[src + rest];
                vl = ((const float4*)g_elo)[src + rest];
            }
            ((float4*)(gsm + SA_HI))[t] = vh;
            ((float4*)(gsm + SA_LO))[t] = vl;
        }
        __syncthreads();

        // ---- compute: 8 k8-steps, 3 dependency-free passes each ----
        #pragma unroll
        for (int ksl = 0; ksl < 8; ksl++) {
            int ksg = kc * 8 + ksl;
            uint4 ah[4], al[4];
            #pragma unroll
            for (int i = 0; i < 4; i++) {
                int idx = ((warpM * 4 + i) * 8 + ksl) * 32 + lane;
                ah[i] = ((const uint4*)(gsm + SA_HI))[idx];
                al[i] = ((const uint4*)(gsm + SA_LO))[idx];
            }
            uint2 bh[4], bl[4];
            #pragma unroll
            for (int j = 0; j < 4; j++) {
                int idx = ((warpN * 4 + j) * 16 + ksg) * 32 + lane;
                bh[j] = ((const uint2*)(gsm + SB_HI))[idx];
                bl[j] = ((const uint2*)(gsm + SB_LO))[idx];
            }
            // pass 1: ah * bh  (16 independent MMAs)
            #pragma unroll
            for (int j = 0; j < 4; j++)
                #pragma unroll
                for (int i = 0; i < 4; i++) {
                    float* d = acc[i][j];
                    mma_tf32(d[0], d[1], d[2], d[3],
                             ah[i].x, ah[i].y, ah[i].z, ah[i].w, bh[j].x, bh[j].y);
                }
            // pass 2: ah * bl
            #pragma unroll
            for (int j = 0; j < 4; j++)
                #pragma unroll
                for (int i = 0; i < 4; i++) {
                    float* d = acc[i][j];
                    mma_tf32(d[0], d[1], d[2], d[3],
                             ah[i].x, ah[i].y, ah[i].z, ah[i].w, bl[j].x, bl[j].y);
                }
            // pass 3: al * bh
            #pragma unroll
            for (int j = 0; j < 4; j++)
                #pragma unroll
                for (int i = 0; i < 4; i++) {
                    float* d = acc[i][j];
                    mma_tf32(d[0], d[1], d[2], d[3],
                             al[i].x, al[i].y, al[i].z, al[i].w, bh[j].x, bh[j].y);
                }
        }
    }

    // ---- epilogue: add b1 (P half), store float2 pairs ----
    int mbase = mbase16 * 16;
    #pragma unroll
    for (int j = 0; j < 4; j++) {
        int col = nbase + warpN * 32 + j * 8 + 2 * tg;   // even
        float2 bv = make_float2(0.f, 0.f);
        if (col < H4) bv = *(const float2*)(b1 + col);
        #pragma unroll
        for (int i = 0; i < 4; i++) {
            int row0 = mbase + warpM * 64 + i * 16 + gquad;
            float* d = acc[i][j];
            if (row0 < NN)
                *(float2*)(g_PQ + (size_t)row0 * PQW + col) =
                    make_float2(d[0] + bv.x, d[1] + bv.y);
            if (row0 + 8 < NN)
                *(float2*)(g_PQ + (size_t)(row0 + 8) * PQW + col) =
                    make_float2(d[2] + bv.x, d[3] + bv.y);
        }
    }
}

// ---------------- K2: edge attention, one warp per edge (b1 pre-folded into P) ----------------
__global__ __launch_bounds__(256) void k_edge_att(const int* __restrict__ ei,
                                                  const float* __restrict__ W2,
                                                  const float* __restrict__ b2,
                                                  float* __restrict__ out) {
    __shared__ __align__(16) float sw2[H4];
    int tid = threadIdx.x;
    for (int i = tid; i < H4; i += blockDim.x) sw2[i] = W2[i];
    __syncthreads();

    int gw   = (blockIdx.x * blockDim.x + tid) >> 5;
    int lane = tid & 31;
    if (gw >= NE) return;
    int r = ei[gw];
    int c = ei[NE + gw];
    const float4* Pr = (const float4*)(g_PQ + (size_t)r * PQW);
    const float4* Qr = (const float4*)(g_PQ + (size_t)c * PQW + H4);
    const float4* W4 = (const float4*)sw2;

    float acc = 0.f;
    #pragma unroll
    for (int it = 0; it < 4; it++) {
        int j4 = it * 32 + lane;
        float4 p = Pr[j4];
        float4 q = Qr[j4];
        float4 ww = W4[j4];
        acc += ww.x * fmaxf(p.x + q.x, 0.f);
        acc += ww.y * fmaxf(p.y + q.y, 0.f);
        acc += ww.z * fmaxf(p.z + q.z, 0.f);
        acc += ww.w * fmaxf(p.w + q.w, 0.f);
    }
    #pragma unroll
    for (int off = 16; off > 0; off >>= 1)
        acc += __shfl_xor_sync(0xFFFFFFFFu, acc, off);
    if (lane == 0) out[O_ATT + gw] = acc + b2[0];
}

// ---------------- K3: per-graph top-k radix select (512 thr, shuffle scans) ----------------
__global__ __launch_bounds__(512) void k_select(const int* __restrict__ ei,
                                                float* __restrict__ out) {
    __shared__ unsigned int skey[EPG];     // 16KB
    __shared__ int hist[256];
    __shared__ int wtmp[16];
    __shared__ unsigned int s_prefix;
    __shared__ int s_kleft;

    int g    = blockIdx.x;
    int tid  = threadIdx.x;
    int lane = tid & 31;
    int wid  = tid >> 5;
    int base = g * EPG;

    for (int i = tid; i < EPG; i += 512) skey[i] = f2k(out[O_ATT + base + i]);
    __syncthreads();

    unsigned int prefix = 0u;
    int kleft = KSEL;
    #pragma unroll
    for (int pass = 3; pass >= 0; pass--) {
        int shift = pass * 8;
        if (tid < 256) hist[tid] = 0;
        __syncthreads();
        unsigned int maskHigh = (pass == 3) ? 0u : (0xFFFFFFFFu << (shift + 8));
        for (int i = tid; i < EPG; i += 512) {
            unsigned int k = skey[i];
            if ((k & maskHigh) == prefix)
                atomicAdd(&hist[(k >> shift) & 255], 1);
        }
        __syncthreads();
        int myh = 0, sfx = 0;
        if (tid < 256) {
            myh = hist[tid];
            sfx = myh;
            #pragma unroll
            for (int off = 1; off < 32; off <<= 1) {
                int t = __shfl_down_sync(0xFFFFFFFFu, sfx, off);
                if (lane + off < 32) sfx += t;
            }
            if (lane == 0) wtmp[wid] = sfx;
        }
        __syncthreads();
        if (tid < 32) {
            int v = (tid < 8) ? wtmp[tid] : 0;
            #pragma unroll
            for (int off = 1; off < 8; off <<= 1) {
                int t = __shfl_down_sync(0xFFFFFFFFu, v, off);
                if (tid + off < 8) v += t;
            }
            if (tid < 8) wtmp[8 + tid] = v;
        }
        __syncthreads();
        if (tid < 256) {
            int incl  = sfx + ((wid < 7) ? wtmp[8 + wid + 1] : 0);
            int above = incl - myh;
            if (above < kleft && incl >= kleft) {
                s_prefix = prefix | ((unsigned int)tid << shift);
                s_kleft  = kleft - above;
            }
        }
        __syncthreads();
        prefix = s_prefix;
        kleft  = s_kleft;
    }
    __syncthreads();
    unsigned int T = prefix;
    int need = kleft;

    // ordered prefix over equality flags; 512*8=4096 > EPG=4000 -> guard everything
    int start = tid * 8;
    int localEq = 0;
    #pragma unroll
    for (int i = 0; i < 8; i++) {
        int idx = start + i;
        if (idx < EPG) localEq += (skey[idx] == T);
    }
    int p = localEq;
    #pragma unroll
    for (int off = 1; off < 32; off <<= 1) {
        int t = __shfl_up_sync(0xFFFFFFFFu, p, off);
        if (lane >= off) p += t;
    }
    if (lane == 31) wtmp[wid] = p;
    __syncthreads();
    if (tid < 32) {
        int v = (tid < 16) ? wtmp[tid] : 0;
        #pragma unroll
        for (int off = 1; off < 16; off <<= 1) {
            int t = __shfl_up_sync(0xFFFFFFFFu, v, off);
            if (tid >= off) v += t;
        }
        if (tid < 16) wtmp[tid] = v;
    }
    __syncthreads();
    int run = (p - localEq) + ((wid > 0) ? wtmp[wid - 1] : 0);

    for (int i = start; i < start + 8 && i < EPG; i++) {
        unsigned int k = skey[i];
        bool causal;
        if (k > T)       causal = true;
        else if (k == T) { causal = (run < need); run++; }
        else             causal = false;
        float att = k2f(k);
        int e = base + i;
        out[O_CW + e] = causal ? att : 0.f;
        out[O_SW + e] = causal ? 0.f : att;
        out[O_CM + e] = causal ? 1.f : 0.f;
        g_cmask[e] = causal ? 1 : 0;
        if (causal) {
            g_nm[ei[e]]      = 1;
            g_nm[ei[NE + e]] = 1;
        }
    }
}

// ---------------- K4/K5: two-level scan of node mask ----------------
__global__ __launch_bounds__(512) void k_scan_a() {
    __shared__ int s[512];
    int tid = threadIdx.x;
    int n = blockIdx.x * 512 + tid;
    int x = (n < NN) ? g_nm[n] : 0;
    s[tid] = x;
    __syncthreads();
    for (int off = 1; off < 512; off <<= 1) {
        int v = (tid >= off) ? s[tid - off] : 0;
        __syncthreads();
        s[tid] += v;
        __syncthreads();
    }
    if (n < NN) g_scan[n] = s[tid];
    if (tid == 511) g_bsum[blockIdx.x] = s[511];
}

__global__ void k_scan_b(int nblk) {
    if (threadIdx.x == 0 && blockIdx.x == 0) {
        int running = 0;
        for (int b = 0; b < nblk; b++) {
            int t = g_bsum[b];
            g_bsum[b] = running;
            running += t;
        }
    }
}

// ---------------- K6: fused node finalize (new_id, node_mask) + causal_x copy ----------------
__global__ void k_nodes(const float* __restrict__ emb, float* __restrict__ out) {
    int i = blockIdx.x * blockDim.x + threadIdx.x;
    if (i >= NN * 32) return;
    int node = i >> 5;
    int nmv = g_nm[node];
    float4 v = make_float4(0.f, 0.f, 0.f, 0.f);
    if (nmv) v = ((const float4*)emb)[i];
    ((float4*)(out + O_CX))[i] = v;
    if ((i & 31) == 0) {
        out[O_NM + node] = nmv ? 1.f : 0.f;
        g_newid[node] = g_scan[node] + g_bsum[node >> 9] - 1;
    }
}

// ---------------- K7: relabeled edge index ----------------
__global__ void k_edge_out(const int* __restrict__ ei, float* __restrict__ out) {
    int e = blockIdx.x * blockDim.x + threadIdx.x;
    if (e >= NE) return;
    bool c = g_cmask[e] != 0;
    int r = ei[e], cc = ei[NE + e];
    out[O_EI + e]      = c ? (float)g_newid[r]  : -1.f;
    out[O_EI + NE + e] = c ? (float)g_newid[cc] : -1.f;
}

// ---------------- launch ----------------
extern "C" void kernel_launch(void* const* d_in, const int* in_sizes, int n_in,
                              void* d_out, int out_size) {
    const float* emb = (const float*)d_in[0];
    const int*   ei  = (const int*)d_in[1];
    // d_in[2] = node_batch (implied by layout: graph = e / EPG)
    const float* W1  = (const float*)d_in[3];
    const float* b1  = (const float*)d_in[4];
    const float* W2  = (const float*)d_in[5];
    const float* b2  = (const float*)d_in[6];
    float* out = (float*)d_out;

    k_zero_nm<<<(NN + 255) / 256, 256>>>();
    k_split_emb<<<MT_TOT * 16 / 8, 256>>>(emb);    // 6250 blocks
    k_split_w<<<2048 / 8, 256>>>(W1);              // 256 blocks

    cudaFuncSetAttribute(k_gemm_mma, cudaFuncAttributeMaxDynamicSharedMemorySize, GEMM_DYN);
    dim3 ggrid(PQW / 128, (NN + 127) / 128);   // (8, 391)
    k_gemm_mma<<<ggrid, 256, GEMM_DYN>>>(b1);

    k_edge_att<<<(NE * 32 + 255) / 256, 256>>>(ei, W2, b2, out);

    k_select<<<NG, 512>>>(ei, out);

    int nblk = (NN + 511) / 512;            // 98
    k_scan_a<<<nblk, 512>>>();
    k_scan_b<<<1, 32>>>(nblk);

    k_nodes<<<(NN * 32 + 255) / 256, 256>>>(emb, out);
    k_edge_out<<<(NE + 255) / 256, 256>>>(ei, out);
}

// round 10
// speedup vs baseline: 1.4723x; 1.3674x over previous
#include <cuda_runtime.h>
#include <cuda_fp16.h>
#include <cstdint>
#include <math.h>

// ---------------- problem constants (fixed by reference) ----------------
#define NG   100
#define NPG  500
#define EPG  4000
#define NN   (NG*NPG)      // 50000 nodes
#define NE   (NG*EPG)      // 400000 edges
#define HID  128
#define H4   512
#define PQW  1024          // P (512) || Q (512)
#define KSEL 2000          // ceil(0.5 * 4000)
#define MT_TOT 3125        // NN/16 m16-tiles

// output layout (float32, concatenated in reference return order)
#define O_ATT 0
#define O_CW  (NE)
#define O_SW  (2*NE)
#define O_CM  (3*NE)
#define O_EI  (4*NE)           // [2,E]: new_row then new_col
#define O_NM  (6*NE)
#define O_CX  (6*NE + NN)

// ---------------- scratch (__device__ globals; no allocation) ----------------
// A fragments (fp16x2-packed): [mt 3125][ks16 8][lane 32] -> uint4 {a0,a1,a2,a3}
__device__ uint4         g_ehi[(size_t)MT_TOT * 8 * 32];
__device__ uint4         g_elo[(size_t)MT_TOT * 8 * 32];
// B fragments: [half 2][nt 64][ks16 8][lane 32] -> uint2 {b0,b1}
__device__ uint2         g_wthi[2 * 64 * 8 * 32];
__device__ uint2         g_wtlo[2 * 64 * 8 * 32];
__device__ float         g_PQ[(size_t)NN * PQW];    // ~205 MB
__device__ unsigned char g_cmask[NE];
__device__ int           g_nm[NN];
__device__ int           g_scan[NN];
__device__ int           g_newid[NN];
__device__ int           g_bsum[128];

// ---------------- helpers ----------------
__device__ __forceinline__ unsigned int h2u(__half2 h) { return *(unsigned int*)&h; }

__device__ __forceinline__ void split_f2(float2 v, unsigned int& hi, unsigned int& lo) {
    __half2 h = __float22half2_rn(v);
    float2 hf = __half22float2(h);
    __half2 l = __float22half2_rn(make_float2(v.x - hf.x, v.y - hf.y));
    hi = h2u(h); lo = h2u(l);
}

__device__ __forceinline__ unsigned int f2k(float f) {
    unsigned int u = __float_as_uint(f);
    return (u & 0x80000000u) ? ~u : (u | 0x80000000u);
}
__device__ __forceinline__ float k2f(unsigned int k) {
    unsigned int u = (k & 0x80000000u) ? (k & 0x7FFFFFFFu) : ~k;
    return __uint_as_float(u);
}

// ---------------- warp-level fp16 MMA m16n8k16 (baseline PTX) ----------------
__device__ __forceinline__ void mma_f16(float* d, uint4 a, uint2 b) {
    asm volatile(
        "mma.sync.aligned.m16n8k16.row.col.f32.f16.f16.f32 "
        "{%0,%1,%2,%3}, {%4,%5,%6,%7}, {%8,%9}, {%0,%1,%2,%3};"
        : "+f"(d[0]), "+f"(d[1]), "+f"(d[2]), "+f"(d[3])
        : "r"(a.x), "r"(a.y), "r"(a.z), "r"(a.w), "r"(b.x), "r"(b.y));
}

// ---------------- K0: zero node-mask ----------------
__global__ void k_zero_nm() {
    int n = blockIdx.x * blockDim.x + threadIdx.x;
    if (n < NN) g_nm[n] = 0;
}

// ---------------- K-split: emb -> fp16 hi/lo fragments ----------------
// one warp per (mt, ks16): lane (g,t) packs a0={A[r,c],A[r,c+1]}, a1={A[r+8,c],...},
// a2={A[r,c+8],A[r,c+9]}, a3={A[r+8,c+8],...}; r=mt*16+g, c=ks*16+2t.
__global__ __launch_bounds__(256) void k_split_emb(const float* __restrict__ emb) {
    int wid  = threadIdx.x >> 5;
    int lane = threadIdx.x & 31;
    int g = lane >> 2, t = lane & 3;
    int task = blockIdx.x * 8 + wid;        // 0 .. 25000-1 exact
    int mt = task >> 3;
    int ks = task & 7;
    int r0 = mt * 16 + g;
    int c0 = ks * 16 + 2 * t;
    float2 v00 = *(const float2*)(emb + (size_t)r0 * HID + c0);
    float2 v10 = *(const float2*)(emb + (size_t)(r0 + 8) * HID + c0);
    float2 v02 = *(const float2*)(emb + (size_t)r0 * HID + c0 + 8);
    float2 v12 = *(const float2*)(emb + (size_t)(r0 + 8) * HID + c0 + 8);
    uint4 h, l;
    split_f2(v00, h.x, l.x);
    split_f2(v10, h.y, l.y);
    split_f2(v02, h.z, l.z);
    split_f2(v12, h.w, l.w);
    size_t idx = (size_t)task * 32 + lane;
    g_ehi[idx] = h;
    g_elo[idx] = l;
}

// ---------------- K-split: W1 -> fp16 hi/lo fragments ----------------
// one warp per (half, nt, ks16): lane packs b0={B[k,n],B[k+1,n]}, b1={B[k+8,n],B[k+9,n]};
// n=nt*8+g, k=half*128+ks*16+2t; B[k][n] = W1[k*512+n].
__global__ __launch_bounds__(256) void k_split_w(const float* __restrict__ W1) {
    int wid  = threadIdx.x >> 5;
    int lane = threadIdx.x & 31;
    int g = lane >> 2, t = lane & 3;
    int task = blockIdx.x * 8 + wid;        // 0 .. 1023 exact
    int half = task >> 9;
    int nt   = (task >> 3) & 63;
    int ks   = task & 7;
    int n  = nt * 8 + g;
    int k0 = half * 128 + ks * 16 + 2 * t;
    float2 v0 = make_float2(W1[(size_t)k0 * H4 + n], W1[(size_t)(k0 + 1) * H4 + n]);
    float2 v1 = make_float2(W1[(size_t)(k0 + 8) * H4 + n], W1[(size_t)(k0 + 9) * H4 + n]);
    uint2 h, l;
    split_f2(v0, h.x, l.x);
    split_f2(v1, h.y, l.y);
    size_t idx = (size_t)task * 32 + lane;
    g_wthi[idx] = h;
    g_wtlo[idx] = l;
}

// ---------------- K1: 3xFP16 GEMM via mma.sync m16n8k16 ----------------
// grid (16, 391): x = 64-wide n-tile of PQ, y = 128-row m-tile (8 m16-tiles).
// CTA 128m x 64n, 8 warps (warpM 2 x warpN 4), warp = 64m x 16n.
// All operands resident in smem (A 64KB + B 32KB = 96KB) -> 2 CTAs/SM.
// Per k16-step per warp: 8 LDS.128 (A) + 4 LDS.64 (B) + 24 MMAs, pass-split.
#define SB_HI 0          // float offsets
#define SB_LO 4096       // B: 8nt*8ks*32 uint2 = 16KB each
#define SA_HI 8192       // A: 8mt*8ks*32 uint4 = 32KB each
#define SA_LO 16384
#define GEMM_DYN (24576*4)   // 98304 bytes

extern __shared__ float gsm[];

__global__ __launch_bounds__(256, 2) void k_gemm_mma(const float* __restrict__ b1) {
    int tid   = threadIdx.x;
    int wid   = tid >> 5;
    int lane  = tid & 31;
    int gquad = lane >> 2;
    int tg    = lane & 3;
    int nbase = blockIdx.x * 64;
    int mbase16 = blockIdx.y * 8;

    int warpM = wid & 1;                   // 2 x 64 rows
    int warpN = wid >> 1;                  // 4 x 16 cols

    int half = nbase >> 9;                 // 0 = P, 1 = Q
    int ntb  = (nbase & 511) >> 3;         // first n8-tile within half (8 per CTA)

    // ---- stage B (8 nt x 8 ks, hi+lo): contiguous copy ----
    {
        size_t src4 = ((size_t)(half * 64 + ntb) * 256) >> 1;   // float4 index into g_wthi
        const float4* sh = (const float4*)g_wthi + src4;
        const float4* sl = (const float4*)g_wtlo + src4;
        #pragma unroll
        for (int l = 0; l < 4; l++) {
            int t = tid + l * 256;                              // 0..1023 float4
            ((float4*)(gsm + SB_HI))[t] = sh[t];
            ((float4*)(gsm + SB_LO))[t] = sl[t];
        }
    }
    // ---- stage A (8 mt x 8 ks, hi+lo): contiguous copy with mt guard ----
    {
        const float4* sh = (const float4*)g_ehi + (size_t)mbase16 * 256;
        const float4* sl = (const float4*)g_elo + (size_t)mbase16 * 256;
        #pragma unroll
        for (int l = 0; l < 8; l++) {
            int t  = tid + l * 256;                             // 0..2047 float4
            int mt = t >> 8;
            float4 vh = make_float4(0.f, 0.f, 0.f, 0.f), vl = vh;
            if (mbase16 + mt < MT_TOT) { vh = sh[t]; vl = sl[t]; }
            ((float4*)(gsm + SA_HI))[t] = vh;
            ((float4*)(gsm + SA_LO))[t] = vl;
        }
    }
    __syncthreads();

    float acc[4][2][4];
    #pragma unroll
    for (int i = 0; i < 4; i++)
        #pragma unroll
        for (int j = 0; j < 2; j++)
            #pragma unroll
            for (int r = 0; r < 4; r++) acc[i][j][r] = 0.f;

    #pragma unroll
    for (int ks = 0; ks < 8; ks++) {
        uint4 ah[4], al[4];
        #pragma unroll
        for (int i = 0; i < 4; i++) {
            int idx = ((warpM * 4 + i) * 8 + ks) * 32 + lane;
            ah[i] = ((const uint4*)(gsm + SA_HI))[idx];
            al[i] = ((const uint4*)(gsm + SA_LO))[idx];
        }
        uint2 bh[2], bl[2];
        #pragma unroll
        for (int j = 0; j < 2; j++) {
            int idx = ((warpN * 2 + j) * 8 + ks) * 32 + lane;
            bh[j] = ((const uint2*)(gsm + SB_HI))[idx];
            bl[j] = ((const uint2*)(gsm + SB_LO))[idx];
        }
        // pass 1: ah * bh (8 independent MMAs)
        #pragma unroll
        for (int j = 0; j < 2; j++)
            #pragma unroll
            for (int i = 0; i < 4; i++) mma_f16(acc[i][j], ah[i], bh[j]);
        // pass 2: ah * bl
        #pragma unroll
        for (int j = 0; j < 2; j++)
            #pragma unroll
            for (int i = 0; i < 4; i++) mma_f16(acc[i][j], ah[i], bl[j]);
        // pass 3: al * bh
        #pragma unroll
        for (int j = 0; j < 2; j++)
            #pragma unroll
            for (int i = 0; i < 4; i++) mma_f16(acc[i][j], al[i], bh[j]);
    }

    // ---- epilogue: add b1 (P half), store float2 pairs ----
    int mbase = mbase16 * 16;
    #pragma unroll
    for (int j = 0; j < 2; j++) {
        int col = nbase + warpN * 16 + j * 8 + 2 * tg;   // even
        float2 bv = make_float2(0.f, 0.f);
        if (col < H4) bv = *(const float2*)(b1 + col);
        #pragma unroll
        for (int i = 0; i < 4; i++) {
            int row0 = mbase + warpM * 64 + i * 16 + gquad;
            float* d = acc[i][j];
            if (row0 < NN)
                *(float2*)(g_PQ + (size_t)row0 * PQW + col) =
                    make_float2(d[0] + bv.x, d[1] + bv.y);
            if (row0 + 8 < NN)
                *(float2*)(g_PQ + (size_t)(row0 + 8) * PQW + col) =
                    make_float2(d[2] + bv.x, d[3] + bv.y);
        }
    }
}

// ---------------- K2: edge attention, one warp per edge (b1 pre-folded into P) ----------------
__global__ __launch_bounds__(256) void k_edge_att(const int* __restrict__ ei,
                                                  const float* __restrict__ W2,
                                                  const float* __restrict__ b2,
                                                  float* __restrict__ out) {
    __shared__ __align__(16) float sw2[H4];
    int tid = threadIdx.x;
    for (int i = tid; i < H4; i += blockDim.x) sw2[i] = W2[i];
    __syncthreads();

    int gw   = (blockIdx.x * blockDim.x + tid) >> 5;
    int lane = tid & 31;
    if (gw >= NE) return;
    int r = ei[gw];
    int c = ei[NE + gw];
    const float4* Pr = (const float4*)(g_PQ + (size_t)r * PQW);
    const float4* Qr = (const float4*)(g_PQ + (size_t)c * PQW + H4);
    const float4* W4 = (const float4*)sw2;

    float acc = 0.f;
    #pragma unroll
    for (int it = 0; it < 4; it++) {
        int j4 = it * 32 + lane;
        float4 p = Pr[j4];
        float4 q = Qr[j4];
        float4 ww = W4[j4];
        acc += ww.x * fmaxf(p.x + q.x, 0.f);
        acc += ww.y * fmaxf(p.y + q.y, 0.f);
        acc += ww.z * fmaxf(p.z + q.z, 0.f);
        acc += ww.w * fmaxf(p.w + q.w, 0.f);
    }
    #pragma unroll
    for (int off = 16; off > 0; off >>= 1)
        acc += __shfl_xor_sync(0xFFFFFFFFu, acc, off);
    if (lane == 0) out[O_ATT + gw] = acc + b2[0];
}

// ---------------- K3: per-graph top-k radix select (512 thr, shuffle scans) ----------------
__global__ __launch_bounds__(512) void k_select(const int* __restrict__ ei,
                                                float* __restrict__ out) {
    __shared__ unsigned int skey[EPG];     // 16KB
    __shared__ int hist[256];
    __shared__ int wtmp[16];
    __shared__ unsigned int s_prefix;
    __shared__ int s_kleft;

    int g    = blockIdx.x;
    int tid  = threadIdx.x;
    int lane = tid & 31;
    int wid  = tid >> 5;
    int base = g * EPG;

    for (int i = tid; i < EPG; i += 512) skey[i] = f2k(out[O_ATT + base + i]);
    __syncthreads();

    unsigned int prefix = 0u;
    int kleft = KSEL;
    #pragma unroll
    for (int pass = 3; pass >= 0; pass--) {
        int shift = pass * 8;
        if (tid < 256) hist[tid] = 0;
        __syncthreads();
        unsigned int maskHigh = (pass == 3) ? 0u : (0xFFFFFFFFu << (shift + 8));
        for (int i = tid; i < EPG; i += 512) {
            unsigned int k = skey[i];
            if ((k & maskHigh) == prefix)
                atomicAdd(&hist[(k >> shift) & 255], 1);
        }
        __syncthreads();
        int myh = 0, sfx = 0;
        if (tid < 256) {
            myh = hist[tid];
            sfx = myh;
            #pragma unroll
            for (int off = 1; off < 32; off <<= 1) {
                int t = __shfl_down_sync(0xFFFFFFFFu, sfx, off);
                if (lane + off < 32) sfx += t;
            }
            if (lane == 0) wtmp[wid] = sfx;
        }
        __syncthreads();
        if (tid < 32) {
            int v = (tid < 8) ? wtmp[tid] : 0;
            #pragma unroll
            for (int off = 1; off < 8; off <<= 1) {
                int t = __shfl_down_sync(0xFFFFFFFFu, v, off);
                if (tid + off < 8) v += t;
            }
            if (tid < 8) wtmp[8 + tid] = v;
        }
        __syncthreads();
        if (tid < 256) {
            int incl  = sfx + ((wid < 7) ? wtmp[8 + wid + 1] : 0);
            int above = incl - myh;
            if (above < kleft && incl >= kleft) {
                s_prefix = prefix | ((unsigned int)tid << shift);
                s_kleft  = kleft - above;
            }
        }
        __syncthreads();
        prefix = s_prefix;
        kleft  = s_kleft;
    }
    __syncthreads();
    unsigned int T = prefix;
    int need = kleft;

    // ordered prefix over equality flags; 512*8=4096 > EPG=4000 -> guard everything
    int start = tid * 8;
    int localEq = 0;
    #pragma unroll
    for (int i = 0; i < 8; i++) {
        int idx = start + i;
        if (idx < EPG) localEq += (skey[idx] == T);
    }
    int p = localEq;
    #pragma unroll
    for (int off = 1; off < 32; off <<= 1) {
        int t = __shfl_up_sync(0xFFFFFFFFu, p, off);
        if (lane >= off) p += t;
    }
    if (lane == 31) wtmp[wid] = p;
    __syncthreads();
    if (tid < 32) {
        int v = (tid < 16) ? wtmp[tid] : 0;
        #pragma unroll
        for (int off = 1; off < 16; off <<= 1) {
            int t = __shfl_up_sync(0xFFFFFFFFu, v, off);
            if (tid >= off) v += t;
        }
        if (tid < 16) wtmp[tid] = v;
    }
    __syncthreads();
    int run = (p - localEq) + ((wid > 0) ? wtmp[wid - 1] : 0);

    for (int i = start; i < start + 8 && i < EPG; i++) {
        unsigned int k = skey[i];
        bool causal;
        if (k > T)       causal = true;
        else if (k == T) { causal = (run < need); run++; }
        else             causal = false;
        float att = k2f(k);
        int e = base + i;
        out[O_CW + e] = causal ? att : 0.f;
        out[O_SW + e] = causal ? 0.f : att;
        out[O_CM + e] = causal ? 1.f : 0.f;
        g_cmask[e] = causal ? 1 : 0;
        if (causal) {
            g_nm[ei[e]]      = 1;
            g_nm[ei[NE + e]] = 1;
        }
    }
}

// ---------------- K4/K5: two-level scan of node mask ----------------
__global__ __launch_bounds__(512) void k_scan_a() {
    __shared__ int s[512];
    int tid = threadIdx.x;
    int n = blockIdx.x * 512 + tid;
    int x = (n < NN) ? g_nm[n] : 0;
    s[tid] = x;
    __syncthreads();
    for (int off = 1; off < 512; off <<= 1) {
        int v = (tid >= off) ? s[tid - off] : 0;
        __syncthreads();
        s[tid] += v;
        __syncthreads();
    }
    if (n < NN) g_scan[n] = s[tid];
    if (tid == 511) g_bsum[blockIdx.x] = s[511];
}

__global__ void k_scan_b(int nblk) {
    if (threadIdx.x == 0 && blockIdx.x == 0) {
        int running = 0;
        for (int b = 0; b < nblk; b++) {
            int t = g_bsum[b];
            g_bsum[b] = running;
            running += t;
        }
    }
}

// ---------------- K6: fused node finalize (new_id, node_mask) + causal_x copy ----------------
__global__ void k_nodes(const float* __restrict__ emb, float* __restrict__ out) {
    int i = blockIdx.x * blockDim.x + threadIdx.x;
    if (i >= NN * 32) return;
    int node = i >> 5;
    int nmv = g_nm[node];
    float4 v = make_float4(0.f, 0.f, 0.f, 0.f);
    if (nmv) v = ((const float4*)emb)[i];
    ((float4*)(out + O_CX))[i] = v;
    if ((i & 31) == 0) {
        out[O_NM + node] = nmv ? 1.f : 0.f;
        g_newid[node] = g_scan[node] + g_bsum[node >> 9] - 1;
    }
}

// ---------------- K7: relabeled edge index ----------------
__global__ void k_edge_out(const int* __restrict__ ei, float* __restrict__ out) {
    int e = blockIdx.x * blockDim.x + threadIdx.x;
    if (e >= NE) return;
    bool c = g_cmask[e] != 0;
    int r = ei[e], cc = ei[NE + e];
    out[O_EI + e]      = c ? (float)g_newid[r]  : -1.f;
    out[O_EI + NE + e] = c ? (float)g_newid[cc] : -1.f;
}

// ---------------- launch ----------------
extern "C" void kernel_launch(void* const* d_in, const int* in_sizes, int n_in,
                              void* d_out, int out_size) {
    const float* emb = (const float*)d_in[0];
    const int*   ei  = (const int*)d_in[1];
    // d_in[2] = node_batch (implied by layout: graph = e / EPG)
    const float* W1  = (const float*)d_in[3];
    const float* b1  = (const float*)d_in[4];
    const float* W2  = (const float*)d_in[5];
    const float* b2  = (const float*)d_in[6];
    float* out = (float*)d_out;

    k_zero_nm<<<(NN + 255) / 256, 256>>>();
    k_split_emb<<<MT_TOT, 256>>>(emb);        // 3125 blocks x 8 warps = 25000 tasks
    k_split_w<<<128, 256>>>(W1);              // 1024 tasks

    cudaFuncSetAttribute(k_gemm_mma, cudaFuncAttributeMaxDynamicSharedMemorySize, GEMM_DYN);
    dim3 ggrid(PQW / 64, (NN + 127) / 128);   // (16, 391)
    k_gemm_mma<<<ggrid, 256, GEMM_DYN>>>(b1);

    k_edge_att<<<(NE * 32 + 255) / 256, 256>>>(ei, W2, b2, out);

    k_select<<<NG, 512>>>(ei, out);

    int nblk = (NN + 511) / 512;            // 98
    k_scan_a<<<nblk, 512>>>();
    k_scan_b<<<1, 32>>>(nblk);

    k_nodes<<<(NN * 32 + 255) / 256, 256>>>(emb, out);
    k_edge_out<<<(NE + 255) / 256, 256>>>(ei, out);
}